// round 1
// baseline (speedup 1.0000x reference)
#include <cuda_runtime.h>
#include <math.h>

#define BB 2
#define NN 160
#define HH 256
#define C3 768
#define FF 512
#define NP (NN*NN)          // 25600
#define MM (BB*NN)          // 320
#define LOGIT_ELEMS (BB*NP*2)   // 102400 per head
#define EMB_OFF (3*LOGIT_ELEMS) // 307200

// PQ scratch: [head t][half s][m=b*160+n][f]
// s=0: P (multiplies emb[j], W1 rows 0:768), s=1: Q (emb[i], W1 rows 768:1536, +b1 folded)
__device__ float g_PQ[3 * 2 * MM * FF];

// ---------------- Kernel 1: fused GEMM (PQ) + emb_pairs writer ----------------
#define BM 64
#define BN 128
#define BK 16
#define NK (C3/BK)          // 48
#define GEMM_BLOCKS (5*24)  // (320/64) M-tiles * (3 heads * 2 halves * 512/128 f-chunks)
#define ASTRIDE 68

__global__ __launch_bounds__(256) void k1_fused(
    const float* __restrict__ geo, const float* __restrict__ app, const float* __restrict__ con,
    const float* __restrict__ W1c, const float* __restrict__ b1c,
    const float* __restrict__ W1r, const float* __restrict__ b1r,
    const float* __restrict__ W1l, const float* __restrict__ b1l,
    float* __restrict__ out)
{
    __shared__ float As[2][BK*ASTRIDE];
    __shared__ float Bs[2][BK*BN];
    const int g = blockIdx.x;
    const int tid = threadIdx.x;

    if (g < GEMM_BLOCKS) {
        // ---- GEMM role: PQ[t][s] = emb @ W1_t[s*768 : s*768+768] ----
        const int nt = g % 24;
        const int mt = g / 24;
        const int t  = nt >> 3;
        const int s  = (nt >> 2) & 1;
        const int fcb = nt & 3;
        const float* W1 = (t==0 ? W1c : (t==1 ? W1r : W1l)) + (size_t)s * C3 * FF;
        const float* b1 = (t==0 ? b1c : (t==1 ? b1r : b1l));
        const int m0 = mt * BM;
        const int f0 = fcb * BN;

        // compute-thread mapping: 4(M) x 8(N) per thread
        const int rg = tid >> 4;   // 0..15
        const int cg = tid & 15;   // 0..15

        // A-load mapping
        const int ar = tid >> 2, av = tid & 3;
        const int am = m0 + ar;                  // global m row
        // B-load mapping (two float4 per thread)
        const int kr0 = tid >> 5, fv0 = tid & 31;

        float acc[4][8];
        #pragma unroll
        for (int a = 0; a < 4; a++)
            #pragma unroll
            for (int c = 0; c < 8; c++) acc[a][c] = 0.f;

        float4 pa, pb0, pb1;
        // prefetch k-tile 0
        {
            const int c0 = 0;
            const float* segp = geo;
            pa  = *(const float4*)(segp + (size_t)am * HH + av * 4);
            pb0 = *(const float4*)(W1 + (size_t)(c0 + kr0) * FF + f0 + fv0 * 4);
            pb1 = *(const float4*)(W1 + (size_t)(c0 + kr0 + 8) * FF + f0 + fv0 * 4);
        }
        // store tile 0
        {
            As[0][(av*4+0)*ASTRIDE + ar] = pa.x;
            As[0][(av*4+1)*ASTRIDE + ar] = pa.y;
            As[0][(av*4+2)*ASTRIDE + ar] = pa.z;
            As[0][(av*4+3)*ASTRIDE + ar] = pa.w;
            *(float4*)&Bs[0][kr0*BN + fv0*4]     = pb0;
            *(float4*)&Bs[0][(kr0+8)*BN + fv0*4] = pb1;
        }
        __syncthreads();

        for (int kt = 0; kt < NK; kt++) {
            const int cur = kt & 1;
            const int nxt = cur ^ 1;
            if (kt + 1 < NK) {
                const int c0 = (kt + 1) * BK;
                const float* segp = (c0 < 256) ? geo : ((c0 < 512) ? app : con);
                pa  = *(const float4*)(segp + (size_t)am * HH + (c0 & 255) + av * 4);
                pb0 = *(const float4*)(W1 + (size_t)(c0 + kr0) * FF + f0 + fv0 * 4);
                pb1 = *(const float4*)(W1 + (size_t)(c0 + kr0 + 8) * FF + f0 + fv0 * 4);
            }
            #pragma unroll
            for (int k = 0; k < BK; k++) {
                float4 a4 = *(const float4*)&As[cur][k*ASTRIDE + rg*4];
                float4 b4a = *(const float4*)&Bs[cur][k*BN + cg*8];
                float4 b4b = *(const float4*)&Bs[cur][k*BN + cg*8 + 4];
                float avv[4] = {a4.x, a4.y, a4.z, a4.w};
                float bvv[8] = {b4a.x, b4a.y, b4a.z, b4a.w, b4b.x, b4b.y, b4b.z, b4b.w};
                #pragma unroll
                for (int a = 0; a < 4; a++)
                    #pragma unroll
                    for (int c = 0; c < 8; c++)
                        acc[a][c] = fmaf(avv[a], bvv[c], acc[a][c]);
            }
            if (kt + 1 < NK) {
                __syncthreads();
                As[nxt][(av*4+0)*ASTRIDE + ar] = pa.x;
                As[nxt][(av*4+1)*ASTRIDE + ar] = pa.y;
                As[nxt][(av*4+2)*ASTRIDE + ar] = pa.z;
                As[nxt][(av*4+3)*ASTRIDE + ar] = pa.w;
                *(float4*)&Bs[nxt][kr0*BN + fv0*4]     = pb0;
                *(float4*)&Bs[nxt][(kr0+8)*BN + fv0*4] = pb1;
                __syncthreads();
            }
        }

        // epilogue: fold b1 into Q half (s==1)
        #pragma unroll
        for (int a = 0; a < 4; a++) {
            const int m = m0 + rg*4 + a;
            float* dst = g_PQ + ((size_t)((t*2 + s) * MM + m)) * FF + f0 + cg*8;
            float v[8];
            #pragma unroll
            for (int c = 0; c < 8; c++) {
                v[c] = acc[a][c];
                if (s) v[c] += b1[f0 + cg*8 + c];
            }
            *(float4*)(dst)     = make_float4(v[0], v[1], v[2], v[3]);
            *(float4*)(dst + 4) = make_float4(v[4], v[5], v[6], v[7]);
        }
    } else {
        // ---- writer role: emb_pairs[b, i*N+j, :] = concat(emb[b,j], emb[b,i]) ----
        const int pid = g - GEMM_BLOCKS;           // 0 .. 51199
        const int b = pid / NP;
        const int r = pid % NP;
        const int i = r / NN, j = r % NN;
        float4* dst = (float4*)(out + (size_t)EMB_OFF + (size_t)pid * 1536);
        #pragma unroll
        for (int h = 0; h < 2; h++) {
            const int u = tid + h * 256;
            if (u < 384) {
                const int c4 = u * 4;
                const int n = (c4 < 768) ? j : i;
                const int c = (c4 < 768) ? c4 : (c4 - 768);
                const int seg = c >> 8;
                const float* base = (seg == 0) ? geo : ((seg == 1) ? app : con);
                dst[u] = *(const float4*)(base + (size_t)(b * NN + n) * HH + (c & 255));
            }
        }
    }
}

// ---------------- Kernel 2: per-pair logits (relu-dot + sigmoid) ----------------
// grid: (5 j-tiles, 20 i-tiles, 6 = 3 heads * 2 batch); block 256 = 8 warps
// warp w -> i = i0 + w ; lane -> j = j0 + lane
__global__ __launch_bounds__(256) void k2_logits(
    float* __restrict__ out,
    const float* __restrict__ W2c, const float* __restrict__ b2c,
    const float* __restrict__ W2r, const float* __restrict__ b2r,
    const float* __restrict__ W2l, const float* __restrict__ b2l)
{
    __shared__ float sP[32 * 260];
    __shared__ float sQ[8 * 256];
    __shared__ float sW[256];
    const int tid = threadIdx.x;
    const int z = blockIdx.z;
    const int t = z >> 1, b = z & 1;
    const int i0 = blockIdx.y * 8;
    const int j0 = blockIdx.x * 32;
    const float* W2 = (t==0 ? W2c : (t==1 ? W2r : W2l));
    const float* b2 = (t==0 ? b2c : (t==1 ? b2r : b2l));
    const float* Pb = g_PQ + ((size_t)((t*2 + 0) * MM + b * NN)) * FF;
    const float* Qb = g_PQ + ((size_t)((t*2 + 1) * MM + b * NN)) * FF;
    const int il = tid >> 5, jl = tid & 31;

    float acc = 0.f;
    for (int fc = 0; fc < 2; fc++) {
        const int f0 = fc * 256;
        // load P tile: 32 rows x 256 f  (8 float4 per thread)
        {
            const int r = tid >> 3, v = tid & 7;
            const float* src = Pb + (size_t)(j0 + r) * FF + f0;
            float* dstp = sP + r * 260;
            #pragma unroll
            for (int u = 0; u < 8; u++) {
                const int fl = (v + u * 8) * 4;
                *(float4*)(dstp + fl) = *(const float4*)(src + fl);
            }
        }
        // load Q tile: 8 rows x 256 f  (2 float4 per thread)
        {
            #pragma unroll
            for (int h = 0; h < 2; h++) {
                const int idx = tid + h * 256;
                const int r = idx >> 6, v = idx & 63;
                *(float4*)(sQ + r * 256 + v * 4) =
                    *(const float4*)(Qb + (size_t)(i0 + r) * FF + f0 + v * 4);
            }
        }
        // W2 difference column
        {
            const float2 w2v = ((const float2*)W2)[f0 + tid];
            sW[tid] = w2v.x - w2v.y;
        }
        __syncthreads();

        const float* pr = sP + jl * 260;
        const float* qr = sQ + il * 256;
        #pragma unroll 8
        for (int f = 0; f < 256; f += 4) {
            float4 p = *(const float4*)(pr + f);
            float4 q = *(const float4*)(qr + f);
            float4 w = *(const float4*)(sW + f);
            acc = fmaf(fmaxf(p.x + q.x, 0.f), w.x, acc);
            acc = fmaf(fmaxf(p.y + q.y, 0.f), w.y, acc);
            acc = fmaf(fmaxf(p.z + q.z, 0.f), w.z, acc);
            acc = fmaf(fmaxf(p.w + q.w, 0.f), w.w, acc);
        }
        __syncthreads();
    }

    const float d = acc + b2[0] - b2[1];
    const float p0 = 1.0f / (1.0f + __expf(-d));
    const int i = i0 + il, j = j0 + jl;
    float2* o = (float2*)(out + (size_t)t * LOGIT_ELEMS);
    o[b * NP + i * NN + j] = make_float2(p0, 1.0f - p0);
}

extern "C" void kernel_launch(void* const* d_in, const int* in_sizes, int n_in,
                              void* d_out, int out_size) {
    const float* geo = (const float*)d_in[0];
    const float* app = (const float*)d_in[1];
    const float* con = (const float*)d_in[2];
    const float* W1c = (const float*)d_in[3];
    const float* b1c = (const float*)d_in[4];
    const float* W2c = (const float*)d_in[5];
    const float* b2c = (const float*)d_in[6];
    const float* W1r = (const float*)d_in[7];
    const float* b1r = (const float*)d_in[8];
    const float* W2r = (const float*)d_in[9];
    const float* b2r = (const float*)d_in[10];
    const float* W1l = (const float*)d_in[11];
    const float* b1l = (const float*)d_in[12];
    const float* W2l = (const float*)d_in[13];
    const float* b2l = (const float*)d_in[14];
    float* out = (float*)d_out;

    k1_fused<<<GEMM_BLOCKS + BB * NP, 256>>>(geo, app, con,
                                             W1c, b1c, W1r, b1r, W1l, b1l, out);
    dim3 g2(5, 20, 6);
    k2_logits<<<g2, 256>>>(out, W2c, b2c, W2r, b2r, W2l, b2l);
}

// round 2
// speedup vs baseline: 1.0607x; 1.0607x over previous
#include <cuda_runtime.h>
#include <math.h>

#define BB 2
#define NN 160
#define HH 256
#define C3 768
#define FF 512
#define NP (NN*NN)          // 25600
#define MM (BB*NN)          // 320
#define LOGIT_ELEMS (BB*NP*2)   // 102400 per head
#define EMB_OFF (3*LOGIT_ELEMS) // 307200

// PQ scratch: [head t][half s][m][f]; s=0: P (emb[j] @ W1[0:768]),
// s=1: Q (emb[i] @ W1[768:1536], +b1 folded)
__device__ float g_PQ[3 * 2 * MM * FF];

#define FFMA2(acc, a, b) asm("fma.rn.f32x2 %0, %1, %2, %0;" : "+l"(acc) : "l"(a), "l"(b))
#define PACKDUP(d, x)    asm("mov.b64 %0, {%1, %1};" : "=l"(d) : "r"(__float_as_uint(x)))
#define UNPK(lo, hi, v)  asm("mov.b64 {%0, %1}, %2;" : "=r"(lo), "=r"(hi) : "l"(v))

// ---------------- Kernel 1: fused GEMM (PQ) + emb_pairs writer ----------------
#define BM 32
#define BN 128
#define BK 16
#define NK (C3/BK)          // 48
#define AST 34
#define GEMM_BLOCKS (10*24) // 240: 10 M-tiles * (3 heads * 2 halves * 4 f-chunks)
#define WR_BLOCKS 3200      // 2 * 160 * 10 ; 16 pairs each

__global__ __launch_bounds__(256) void k1_fused(
    const float* __restrict__ geo, const float* __restrict__ app, const float* __restrict__ con,
    const float* __restrict__ W1c, const float* __restrict__ b1c,
    const float* __restrict__ W1r, const float* __restrict__ b1r,
    const float* __restrict__ W1l, const float* __restrict__ b1l,
    float* __restrict__ out)
{
    __shared__ float As[2][BK*AST];
    __shared__ float Bs[2][BK*BN];
    const int g = blockIdx.x;
    const int tid = threadIdx.x;

    if (g < GEMM_BLOCKS) {
        const int nt = g % 24;
        const int mt = g / 24;
        const int t  = nt >> 3;
        const int s  = (nt >> 2) & 1;
        const int fcb = nt & 3;
        const float* W1 = (t==0 ? W1c : (t==1 ? W1r : W1l)) + (size_t)s * C3 * FF;
        const float* b1 = (t==0 ? b1c : (t==1 ? b1r : b1l));
        const int m0 = mt * BM;
        const int f0 = fcb * BN;

        const int rg = tid >> 4;   // 0..15 -> 2 m rows
        const int cg = tid & 15;   // 0..15 -> 8 n cols
        const int ar = tid & 127 ? (tid >> 2) : 0; // placated below
        const int arr = tid >> 2;  // 0..31 (valid when tid<128)
        const int av = tid & 3;
        const int kr0 = tid >> 5, fv0 = tid & 31;
        (void)ar;

        unsigned long long acc2[2][4];
        #pragma unroll
        for (int a = 0; a < 2; a++)
            #pragma unroll
            for (int c = 0; c < 4; c++) acc2[a][c] = 0ull;

        float4 pa = make_float4(0.f,0.f,0.f,0.f), pb0, pb1;
        // prefetch k-tile 0 (columns 0..15 -> geo)
        if (tid < 128) pa = *(const float4*)(geo + (size_t)(m0 + arr) * HH + av * 4);
        pb0 = *(const float4*)(W1 + (size_t)kr0 * FF + f0 + fv0 * 4);
        pb1 = *(const float4*)(W1 + (size_t)(kr0 + 8) * FF + f0 + fv0 * 4);

        if (tid < 128) {
            As[0][(av*4+0)*AST + arr] = pa.x;
            As[0][(av*4+1)*AST + arr] = pa.y;
            As[0][(av*4+2)*AST + arr] = pa.z;
            As[0][(av*4+3)*AST + arr] = pa.w;
        }
        *(float4*)&Bs[0][kr0*BN + fv0*4]     = pb0;
        *(float4*)&Bs[0][(kr0+8)*BN + fv0*4] = pb1;
        __syncthreads();

        for (int kt = 0; kt < NK; kt++) {
            const int cur = kt & 1;
            const int nxt = cur ^ 1;
            if (kt + 1 < NK) {
                const int c0 = (kt + 1) * BK;
                const float* segp = (c0 < 256) ? geo : ((c0 < 512) ? app : con);
                if (tid < 128)
                    pa = *(const float4*)(segp + (size_t)(m0 + arr) * HH + (c0 & 255) + av * 4);
                pb0 = *(const float4*)(W1 + (size_t)(c0 + kr0) * FF + f0 + fv0 * 4);
                pb1 = *(const float4*)(W1 + (size_t)(c0 + kr0 + 8) * FF + f0 + fv0 * 4);
            }
            #pragma unroll
            for (int k = 0; k < BK; k++) {
                float2 a2 = *(const float2*)&As[cur][k*AST + rg*2];
                unsigned long long pa0, pa1;
                PACKDUP(pa0, a2.x);
                PACKDUP(pa1, a2.y);
                const ulonglong2* bp = (const ulonglong2*)&Bs[cur][k*BN + cg*8];
                ulonglong2 b01 = bp[0];
                ulonglong2 b23 = bp[1];
                FFMA2(acc2[0][0], pa0, b01.x);
                FFMA2(acc2[0][1], pa0, b01.y);
                FFMA2(acc2[0][2], pa0, b23.x);
                FFMA2(acc2[0][3], pa0, b23.y);
                FFMA2(acc2[1][0], pa1, b01.x);
                FFMA2(acc2[1][1], pa1, b01.y);
                FFMA2(acc2[1][2], pa1, b23.x);
                FFMA2(acc2[1][3], pa1, b23.y);
            }
            if (kt + 1 < NK) {
                __syncthreads();
                if (tid < 128) {
                    As[nxt][(av*4+0)*AST + arr] = pa.x;
                    As[nxt][(av*4+1)*AST + arr] = pa.y;
                    As[nxt][(av*4+2)*AST + arr] = pa.z;
                    As[nxt][(av*4+3)*AST + arr] = pa.w;
                }
                *(float4*)&Bs[nxt][kr0*BN + fv0*4]     = pb0;
                *(float4*)&Bs[nxt][(kr0+8)*BN + fv0*4] = pb1;
                __syncthreads();
            }
        }

        // epilogue: unpack, fold b1 into Q half (s==1)
        #pragma unroll
        for (int a = 0; a < 2; a++) {
            const int m = m0 + rg*2 + a;
            float v[8];
            #pragma unroll
            for (int c = 0; c < 4; c++) {
                unsigned int lo, hi;
                UNPK(lo, hi, acc2[a][c]);
                v[2*c]   = __uint_as_float(lo);
                v[2*c+1] = __uint_as_float(hi);
            }
            if (s) {
                #pragma unroll
                for (int c = 0; c < 8; c++) v[c] += b1[f0 + cg*8 + c];
            }
            float* dst = g_PQ + ((size_t)((t*2 + s) * MM + m)) * FF + f0 + cg*8;
            *(float4*)(dst)     = make_float4(v[0], v[1], v[2], v[3]);
            *(float4*)(dst + 4) = make_float4(v[4], v[5], v[6], v[7]);
        }
    } else {
        // ---- writer: 16 pairs (same i-row) per block ----
        const int wb = g - GEMM_BLOCKS;        // 0..3199
        const int b = wb / 1600;
        const int rem = wb % 1600;
        const int i = rem / 10;
        const int j0 = (rem % 10) * 16;
        const size_t brow = (size_t)b * NN * HH;
        float4* dst0 = (float4*)(out + EMB_OFF) + (size_t)(b*NP + i*NN + j0) * 384;

        // per-pair layout: float4 u in [0,384): u<192 = emb[j], u>=192 = emb[i]
        // this thread owns: u=tid always; plus u=tid+256 if tid<128 (emb[i] side)
        float4 hiv0 = make_float4(0,0,0,0), hiv1 = make_float4(0,0,0,0);
        const bool own_hi0 = (tid >= 192);     // u = tid in emb[i] half
        const bool own_hi1 = (tid < 128);      // u = tid+256 (always emb[i] half)
        if (own_hi0) {
            const int c = (tid - 192) * 4;
            const float* base = (c < 256 ? geo : (c < 512 ? app : con)) + brow + (size_t)i*HH + (c & 255);
            hiv0 = *(const float4*)base;
        }
        if (own_hi1) {
            const int c = (tid + 64) * 4;      // (tid+256-192)*4
            const float* base = (c < 256 ? geo : (c < 512 ? app : con)) + brow + (size_t)i*HH + (c & 255);
            hiv1 = *(const float4*)base;
        }
        const float* jbase = 0;
        if (tid < 192) {
            const int c = tid * 4;
            jbase = (c < 256 ? geo : (c < 512 ? app : con)) + brow + (c & 255);
        }
        #pragma unroll 4
        for (int jj = 0; jj < 16; jj++) {
            float4* dst = dst0 + (size_t)jj * 384;
            if (tid < 192) {
                float4 v = *(const float4*)(jbase + (size_t)(j0 + jj) * HH);
                __stcs(dst + tid, v);
            } else {
                __stcs(dst + tid, hiv0);
            }
            if (own_hi1) __stcs(dst + tid + 256, hiv1);
        }
    }
}

// ---------------- Kernel 2: per-pair logits, 32i x 32j tiles ----------------
// grid (5 j-tiles, 5 i-tiles, 6 = 3 heads * 2 batch); block 256
// thread: jl = lane (j), warp il covers 4 i rows (acc[4])
__global__ __launch_bounds__(256) void k2_logits(
    float* __restrict__ out,
    const float* __restrict__ W2c, const float* __restrict__ b2c,
    const float* __restrict__ W2r, const float* __restrict__ b2r,
    const float* __restrict__ W2l, const float* __restrict__ b2l)
{
    __shared__ float sP[32 * 132];
    __shared__ float sQ[32 * 128];
    __shared__ float sW[128];
    const int tid = threadIdx.x;
    const int z = blockIdx.z;
    const int t = z >> 1, b = z & 1;
    const int i0 = blockIdx.y * 32;
    const int j0 = blockIdx.x * 32;
    const float* W2 = (t==0 ? W2c : (t==1 ? W2r : W2l));
    const float* b2 = (t==0 ? b2c : (t==1 ? b2r : b2l));
    const float* Pb = g_PQ + ((size_t)((t*2 + 0) * MM + b * NN)) * FF;
    const float* Qb = g_PQ + ((size_t)((t*2 + 1) * MM + b * NN)) * FF;
    const int il = tid >> 5, jl = tid & 31;
    const int lr = tid >> 3, lv = tid & 7;

    float acc[4] = {0.f, 0.f, 0.f, 0.f};
    for (int fc = 0; fc < 4; fc++) {
        const int f0 = fc * 128;
        {
            const float* src = Pb + (size_t)(j0 + lr) * FF + f0;
            float* dp = sP + lr * 132;
            #pragma unroll
            for (int u = 0; u < 4; u++) {
                const int fl = (lv + u * 8) * 4;
                *(float4*)(dp + fl) = *(const float4*)(src + fl);
            }
        }
        {
            const float* src = Qb + (size_t)(i0 + lr) * FF + f0;
            float* dp = sQ + lr * 128;
            #pragma unroll
            for (int u = 0; u < 4; u++) {
                const int fl = (lv + u * 8) * 4;
                *(float4*)(dp + fl) = *(const float4*)(src + fl);
            }
        }
        if (tid < 128) {
            const float2 w2v = ((const float2*)W2)[f0 + tid];
            sW[tid] = w2v.x - w2v.y;
        }
        __syncthreads();

        const float* pr = sP + jl * 132;
        const float* q0 = sQ + (il * 4) * 128;
        #pragma unroll 4
        for (int f = 0; f < 128; f += 4) {
            const float4 p = *(const float4*)(pr + f);
            const float4 w = *(const float4*)(sW + f);
            #pragma unroll
            for (int a = 0; a < 4; a++) {
                const float4 q = *(const float4*)(q0 + a * 128 + f);
                acc[a] = fmaf(fmaxf(p.x + q.x, 0.f), w.x, acc[a]);
                acc[a] = fmaf(fmaxf(p.y + q.y, 0.f), w.y, acc[a]);
                acc[a] = fmaf(fmaxf(p.z + q.z, 0.f), w.z, acc[a]);
                acc[a] = fmaf(fmaxf(p.w + q.w, 0.f), w.w, acc[a]);
            }
        }
        __syncthreads();
    }

    const float bd = b2[0] - b2[1];
    float2* o = (float2*)(out + (size_t)t * LOGIT_ELEMS) + (size_t)b * NP;
    const int j = j0 + jl;
    #pragma unroll
    for (int a = 0; a < 4; a++) {
        const float d = acc[a] + bd;
        const float p0 = 1.0f / (1.0f + __expf(-d));
        o[(size_t)(i0 + il*4 + a) * NN + j] = make_float2(p0, 1.0f - p0);
    }
}

extern "C" void kernel_launch(void* const* d_in, const int* in_sizes, int n_in,
                              void* d_out, int out_size) {
    const float* geo = (const float*)d_in[0];
    const float* app = (const float*)d_in[1];
    const float* con = (const float*)d_in[2];
    const float* W1c = (const float*)d_in[3];
    const float* b1c = (const float*)d_in[4];
    const float* W2c = (const float*)d_in[5];
    const float* b2c = (const float*)d_in[6];
    const float* W1r = (const float*)d_in[7];
    const float* b1r = (const float*)d_in[8];
    const float* W2r = (const float*)d_in[9];
    const float* b2r = (const float*)d_in[10];
    const float* W1l = (const float*)d_in[11];
    const float* b1l = (const float*)d_in[12];
    const float* W2l = (const float*)d_in[13];
    const float* b2l = (const float*)d_in[14];
    float* out = (float*)d_out;

    k1_fused<<<GEMM_BLOCKS + WR_BLOCKS, 256>>>(geo, app, con,
                                               W1c, b1c, W1r, b1r, W1l, b1l, out);
    dim3 g2(5, 5, 6);
    k2_logits<<<g2, 256>>>(out, W2c, b2c, W2r, b2r, W2l, b2l);
}

// round 3
// speedup vs baseline: 1.5100x; 1.4236x over previous
#include <cuda_runtime.h>
#include <math.h>

#define BB 2
#define NN 160
#define HH 256
#define C3 768
#define FF 512
#define NP (NN*NN)            // 25600
#define MM (BB*NN)            // 320
#define LOGIT_ELEMS (BB*NP*2) // 102400 per head
#define EMB_OFF (3*LOGIT_ELEMS)

// PQ scratch, split-K: [h = t*2+s][ks][m][f]
// s=0: P (emb[j] @ W1[0:768]); s=1: Q (emb[i] @ W1[768:1536], +b1 folded into ks=0)
__device__ float g_PQ[6 * 2 * MM * FF];

#define FFMA2(acc, a, b) asm("fma.rn.f32x2 %0, %1, %2, %0;" : "+l"(acc) : "l"(a), "l"(b))
#define PACKDUP(d, x)    asm("mov.b64 %0, {%1, %1};" : "=l"(d) : "r"(__float_as_uint(x)))
#define UNPK(lo, hi, v)  asm("mov.b64 {%0, %1}, %2;" : "=r"(lo), "=r"(hi) : "l"(v))

// ---------------- Kernel 1: fused split-K GEMM + emb_pairs writer ----------------
// GEMM: BM=64, BN=64, BK=16, 64 threads, per-thread tile 8m x 8n (f32x2 packed on n)
#define BM 64
#define BN 64
#define BK 16
#define NKS 24              // k-tiles per K-slice (384/16)
#define AST 68
#define GEMM_BLOCKS 480     // 5 m-tiles * 2 k-slices * 48 (3 heads * 2 halves * 8 f-chunks)
#define WR_BLOCKS 6400      // 2 * 160 * 20, 8 pairs each

__global__ __launch_bounds__(64) void k1_fused(
    const float* __restrict__ geo, const float* __restrict__ app, const float* __restrict__ con,
    const float* __restrict__ W1c, const float* __restrict__ b1c,
    const float* __restrict__ W1r, const float* __restrict__ b1r,
    const float* __restrict__ W1l, const float* __restrict__ b1l,
    float* __restrict__ out)
{
    __shared__ float As[2][BK*AST];
    __shared__ float Bs[2][BK*BN];
    const int g = blockIdx.x;
    const int tid = threadIdx.x;

    if (g < GEMM_BLOCKS) {
        const int nt = g % 48;
        const int r  = g / 48;          // 0..9
        const int mt = r >> 1;          // 0..4
        const int ks = r & 1;           // K-slice
        const int t  = nt >> 4;
        const int s  = (nt >> 3) & 1;
        const int fcb = nt & 7;
        const float* W1 = (t==0 ? W1c : (t==1 ? W1r : W1l)) + (size_t)s * C3 * FF;
        const float* b1 = (t==0 ? b1c : (t==1 ? b1r : b1l));
        const int m0 = mt * BM;
        const int f0 = fcb * BN;
        const int kbase = ks * 384;

        const int rg = tid >> 3;        // 0..7 -> m rows m0 + rg*8 + a
        const int cg = tid & 7;         // 0..7 -> n cols f0 + cg*8
        const int kr = tid >> 2;        // 0..15 B-load row
        const int fo = (tid & 3) * 16;  // B-load float offset within BN

        unsigned long long acc2[8][4];
        #pragma unroll
        for (int a = 0; a < 8; a++)
            #pragma unroll
            for (int c = 0; c < 4; c++) acc2[a][c] = 0ull;

        float4 pa[4], pb[4];
        // prefetch k-tile 0
        {
            const int c0 = kbase;
            const float* segp = (c0 < 256) ? geo : ((c0 < 512) ? app : con);
            const float* arow = segp + (size_t)(m0 + tid) * HH + (c0 & 255);
            #pragma unroll
            for (int u = 0; u < 4; u++) pa[u] = *(const float4*)(arow + u * 4);
            const float* brow = W1 + (size_t)(c0 + kr) * FF + f0 + fo;
            #pragma unroll
            for (int u = 0; u < 4; u++) pb[u] = *(const float4*)(brow + u * 4);
        }
        {
            float av[16];
            #pragma unroll
            for (int u = 0; u < 4; u++) {
                av[u*4+0]=pa[u].x; av[u*4+1]=pa[u].y; av[u*4+2]=pa[u].z; av[u*4+3]=pa[u].w;
            }
            #pragma unroll
            for (int c = 0; c < 16; c++) As[0][c*AST + tid] = av[c];
            #pragma unroll
            for (int u = 0; u < 4; u++) *(float4*)&Bs[0][kr*BN + fo + u*4] = pb[u];
        }
        __syncthreads();

        for (int kt = 0; kt < NKS; kt++) {
            const int cur = kt & 1;
            const int nxt = cur ^ 1;
            if (kt + 1 < NKS) {
                const int c0 = kbase + (kt + 1) * BK;
                const float* segp = (c0 < 256) ? geo : ((c0 < 512) ? app : con);
                const float* arow = segp + (size_t)(m0 + tid) * HH + (c0 & 255);
                #pragma unroll
                for (int u = 0; u < 4; u++) pa[u] = *(const float4*)(arow + u * 4);
                const float* brow = W1 + (size_t)(c0 + kr) * FF + f0 + fo;
                #pragma unroll
                for (int u = 0; u < 4; u++) pb[u] = *(const float4*)(brow + u * 4);
            }
            #pragma unroll
            for (int k = 0; k < BK; k++) {
                const float4 a0 = *(const float4*)&As[cur][k*AST + rg*8];
                const float4 a1 = *(const float4*)&As[cur][k*AST + rg*8 + 4];
                const ulonglong2 b01 = *(const ulonglong2*)&Bs[cur][k*BN + cg*8];
                const ulonglong2 b23 = *(const ulonglong2*)&Bs[cur][k*BN + cg*8 + 4];
                float avv[8] = {a0.x, a0.y, a0.z, a0.w, a1.x, a1.y, a1.z, a1.w};
                #pragma unroll
                for (int a = 0; a < 8; a++) {
                    unsigned long long ad;
                    PACKDUP(ad, avv[a]);
                    FFMA2(acc2[a][0], ad, b01.x);
                    FFMA2(acc2[a][1], ad, b01.y);
                    FFMA2(acc2[a][2], ad, b23.x);
                    FFMA2(acc2[a][3], ad, b23.y);
                }
            }
            if (kt + 1 < NKS) {
                __syncthreads();
                float av[16];
                #pragma unroll
                for (int u = 0; u < 4; u++) {
                    av[u*4+0]=pa[u].x; av[u*4+1]=pa[u].y; av[u*4+2]=pa[u].z; av[u*4+3]=pa[u].w;
                }
                #pragma unroll
                for (int c = 0; c < 16; c++) As[nxt][c*AST + tid] = av[c];
                #pragma unroll
                for (int u = 0; u < 4; u++) *(float4*)&Bs[nxt][kr*BN + fo + u*4] = pb[u];
                __syncthreads();
            }
        }

        // epilogue: unpack; fold b1 into (s==1, ks==0)
        float bv[8];
        const bool addb = (s == 1) && (ks == 0);
        if (addb) {
            const float4 t0 = *(const float4*)(b1 + f0 + cg*8);
            const float4 t1 = *(const float4*)(b1 + f0 + cg*8 + 4);
            bv[0]=t0.x; bv[1]=t0.y; bv[2]=t0.z; bv[3]=t0.w;
            bv[4]=t1.x; bv[5]=t1.y; bv[6]=t1.z; bv[7]=t1.w;
        }
        const size_t hb = ((size_t)((t*2 + s) * 2 + ks)) * MM * FF;
        #pragma unroll
        for (int a = 0; a < 8; a++) {
            const int m = m0 + rg*8 + a;
            float v[8];
            #pragma unroll
            for (int c = 0; c < 4; c++) {
                unsigned int lo, hi;
                UNPK(lo, hi, acc2[a][c]);
                v[2*c]   = __uint_as_float(lo);
                v[2*c+1] = __uint_as_float(hi);
            }
            if (addb) {
                #pragma unroll
                for (int c = 0; c < 8; c++) v[c] += bv[c];
            }
            float* dst = g_PQ + hb + (size_t)m * FF + f0 + cg*8;
            *(float4*)(dst)     = make_float4(v[0], v[1], v[2], v[3]);
            *(float4*)(dst + 4) = make_float4(v[4], v[5], v[6], v[7]);
        }
    } else {
        // ---- writer: 8 pairs (same i-row) per 64-thread block ----
        const int wb = g - GEMM_BLOCKS;     // 0..6399
        const int b = wb / 3200;
        const int rem = wb % 3200;
        const int i = rem / 20;
        const int j0 = (rem % 20) * 8;
        const size_t brow = (size_t)b * NN * HH;
        const int c = tid * 4;              // 0..252

        // i-half: float4 u-index 192+tid, 256+tid, 320+tid -> segs geo/app/con
        const float4 iv0 = *(const float4*)(geo + brow + (size_t)i*HH + c);
        const float4 iv1 = *(const float4*)(app + brow + (size_t)i*HH + c);
        const float4 iv2 = *(const float4*)(con + brow + (size_t)i*HH + c);
        const float* jg = geo + brow + c;
        const float* ja = app + brow + c;
        const float* jc = con + brow + c;

        float4* dst0 = (float4*)(out + EMB_OFF) + (size_t)(b*NP + i*NN + j0) * 384;
        #pragma unroll
        for (int jj = 0; jj < 8; jj++) {
            const size_t jo = (size_t)(j0 + jj) * HH;
            float4* dst = dst0 + (size_t)jj * 384;
            __stcs(dst + tid,       *(const float4*)(jg + jo));
            __stcs(dst + tid + 64,  *(const float4*)(ja + jo));
            __stcs(dst + tid + 128, *(const float4*)(jc + jo));
            __stcs(dst + tid + 192, iv0);
            __stcs(dst + tid + 256, iv1);
            __stcs(dst + tid + 320, iv2);
        }
    }
}

// ---------------- Kernel 2: per-pair logits, 16i x 32j tiles ----------------
// grid (5 j-tiles, 10 i-tiles, 6 = 3 heads * 2 batch); block 256
__global__ __launch_bounds__(256) void k2_logits(
    float* __restrict__ out,
    const float* __restrict__ W2c, const float* __restrict__ b2c,
    const float* __restrict__ W2r, const float* __restrict__ b2r,
    const float* __restrict__ W2l, const float* __restrict__ b2l)
{
    __shared__ float sP[32 * 132];
    __shared__ float sQ[16 * 128];
    __shared__ float sW[128];
    const int tid = threadIdx.x;
    const int z = blockIdx.z;
    const int t = z >> 1, b = z & 1;
    const int i0 = blockIdx.y * 16;
    const int j0 = blockIdx.x * 32;
    const float* W2 = (t==0 ? W2c : (t==1 ? W2r : W2l));
    const float* b2 = (t==0 ? b2c : (t==1 ? b2r : b2l));
    const float* P0 = g_PQ + ((size_t)((t*2 + 0)*2 + 0)) * MM * FF + (size_t)b * NN * FF;
    const float* P1 = g_PQ + ((size_t)((t*2 + 0)*2 + 1)) * MM * FF + (size_t)b * NN * FF;
    const float* Q0 = g_PQ + ((size_t)((t*2 + 1)*2 + 0)) * MM * FF + (size_t)b * NN * FF;
    const float* Q1 = g_PQ + ((size_t)((t*2 + 1)*2 + 1)) * MM * FF + (size_t)b * NN * FF;
    const int il = tid >> 5, jl = tid & 31;

    float acc[2] = {0.f, 0.f};
    for (int fc = 0; fc < 4; fc++) {
        const int f0 = fc * 128;
        {   // P tile: 32 rows x 128 f (sum of K-slices)
            const int lr = tid >> 3, lv = tid & 7;
            const size_t ro = (size_t)(j0 + lr) * FF + f0;
            float* dp = sP + lr * 132;
            #pragma unroll
            for (int u = 0; u < 4; u++) {
                const int fl = (lv + u * 8) * 4;
                const float4 x = *(const float4*)(P0 + ro + fl);
                const float4 y = *(const float4*)(P1 + ro + fl);
                *(float4*)(dp + fl) = make_float4(x.x+y.x, x.y+y.y, x.z+y.z, x.w+y.w);
            }
        }
        {   // Q tile: 16 rows x 128 f
            const int qr = tid >> 4, qv = tid & 15;
            const size_t ro = (size_t)(i0 + qr) * FF + f0;
            float* dp = sQ + qr * 128;
            #pragma unroll
            for (int u = 0; u < 2; u++) {
                const int fl = (qv + u * 16) * 4;
                const float4 x = *(const float4*)(Q0 + ro + fl);
                const float4 y = *(const float4*)(Q1 + ro + fl);
                *(float4*)(dp + fl) = make_float4(x.x+y.x, x.y+y.y, x.z+y.z, x.w+y.w);
            }
        }
        if (tid < 128) {
            const float2 w2v = ((const float2*)W2)[f0 + tid];
            sW[tid] = w2v.x - w2v.y;
        }
        __syncthreads();

        const float* pr = sP + jl * 132;
        const float* q0 = sQ + (il * 2) * 128;
        const float* q1 = q0 + 128;
        #pragma unroll 8
        for (int f = 0; f < 128; f += 4) {
            const float4 p  = *(const float4*)(pr + f);
            const float4 w  = *(const float4*)(sW + f);
            const float4 qa = *(const float4*)(q0 + f);
            const float4 qb = *(const float4*)(q1 + f);
            acc[0] = fmaf(fmaxf(p.x + qa.x, 0.f), w.x, acc[0]);
            acc[0] = fmaf(fmaxf(p.y + qa.y, 0.f), w.y, acc[0]);
            acc[0] = fmaf(fmaxf(p.z + qa.z, 0.f), w.z, acc[0]);
            acc[0] = fmaf(fmaxf(p.w + qa.w, 0.f), w.w, acc[0]);
            acc[1] = fmaf(fmaxf(p.x + qb.x, 0.f), w.x, acc[1]);
            acc[1] = fmaf(fmaxf(p.y + qb.y, 0.f), w.y, acc[1]);
            acc[1] = fmaf(fmaxf(p.z + qb.z, 0.f), w.z, acc[1]);
            acc[1] = fmaf(fmaxf(p.w + qb.w, 0.f), w.w, acc[1]);
        }
        __syncthreads();
    }

    const float bd = b2[0] - b2[1];
    float2* o = (float2*)(out + (size_t)t * LOGIT_ELEMS) + (size_t)b * NP;
    const int j = j0 + jl;
    #pragma unroll
    for (int a = 0; a < 2; a++) {
        const float d = acc[a] + bd;
        const float p0 = 1.0f / (1.0f + __expf(-d));
        o[(size_t)(i0 + il*2 + a) * NN + j] = make_float2(p0, 1.0f - p0);
    }
}

extern "C" void kernel_launch(void* const* d_in, const int* in_sizes, int n_in,
                              void* d_out, int out_size) {
    const float* geo = (const float*)d_in[0];
    const float* app = (const float*)d_in[1];
    const float* con = (const float*)d_in[2];
    const float* W1c = (const float*)d_in[3];
    const float* b1c = (const float*)d_in[4];
    const float* W2c = (const float*)d_in[5];
    const float* b2c = (const float*)d_in[6];
    const float* W1r = (const float*)d_in[7];
    const float* b1r = (const float*)d_in[8];
    const float* W2r = (const float*)d_in[9];
    const float* b2r = (const float*)d_in[10];
    const float* W1l = (const float*)d_in[11];
    const float* b1l = (const float*)d_in[12];
    const float* W2l = (const float*)d_in[13];
    const float* b2l = (const float*)d_in[14];
    float* out = (float*)d_out;

    k1_fused<<<GEMM_BLOCKS + WR_BLOCKS, 64>>>(geo, app, con,
                                              W1c, b1c, W1r, b1r, W1l, b1l, out);
    dim3 g2(5, 10, 6);
    k2_logits<<<g2, 256>>>(out, W2c, b2c, W2r, b2r, W2l, b2l);
}

// round 4
// speedup vs baseline: 1.6390x; 1.0854x over previous
#include <cuda_runtime.h>
#include <math.h>

#define BB 2
#define NN 160
#define HH 256
#define C3 768
#define FF 512
#define NP (NN*NN)            // 25600
#define MM (BB*NN)            // 320
#define LOGIT_ELEMS (BB*NP*2) // 102400 per head
#define EMB_OFF (3*LOGIT_ELEMS)

// PQ scratch, split-K2: [h = (t*2+s)*2+ks][m][f]
// s=0: P (emb[j] @ W1[0:768]); s=1: Q (emb[i] @ W1[768:1536], b1 folded into ks=0)
__device__ float g_PQ[3 * 2 * 2 * MM * FF];

#define FFMA2(acc, a, b) asm("fma.rn.f32x2 %0, %1, %2, %0;" : "+l"(acc) : "l"(a), "l"(b))
#define PACKDUP(d, x)    asm("mov.b64 %0, {%1, %1};" : "=l"(d) : "r"(__float_as_uint(x)))
#define UNPK(lo, hi, v)  asm("mov.b64 {%0, %1}, %2;" : "=r"(lo), "=r"(hi) : "l"(v))

// ---------------- writer role: 16 pairs (same i) per 256-thread block ----------------
// pair layout (float4 units, 384/pair): u<192 = emb[j] cols u*4, u>=192 = emb[i] cols (u-192)*4
// block-linear dst index = jj*384 + u = v*256 + tid  (perfectly coalesced)
__device__ __forceinline__ void writer_role(
    int b, int i, int j0,
    const float* __restrict__ geo, const float* __restrict__ app, const float* __restrict__ con,
    float* __restrict__ out, int tid)
{
    const size_t brow = (size_t)b * NN * HH;
    float4* dst0 = (float4*)(out + EMB_OFF) + (size_t)(b*NP + i*NN + j0) * 384;
    int u = tid, jj = 0;
    #pragma unroll
    for (int v = 0; v < 24; v++) {
        const bool jside = (u < 192);
        const int n = jside ? (j0 + jj) : i;
        const int c = (jside ? u : (u - 192)) * 4;
        const float* base = (c < 256) ? geo : ((c < 512) ? app : con);
        const float4 val = *(const float4*)(base + brow + (size_t)n * HH + (c & 255));
        __stcs(dst0 + v * 256 + tid, val);
        u += 256;
        if (u >= 384) { u -= 384; ++jj; }
    }
}

// ---------------- Kernel 1: split-K2 GEMM + writer half A ----------------
// GEMM: BM=64, BN=64, BK=16, 256 threads, per-thread 4m x 4n (f32x2 on n)
#define BM 64
#define BN 64
#define BK 16
#define NKS 24              // k-tiles per 384-slice
#define AST 68
#define GEMM_BLOCKS 480     // 5 mt * 2 ks * (3 heads * 2 halves * 8 f-chunks)
#define WRA_BLOCKS 1600     // 2 * 160 * 5 j-tiles (j0 in [0,80))

__global__ __launch_bounds__(256) void k1_gemm_wr(
    const float* __restrict__ geo, const float* __restrict__ app, const float* __restrict__ con,
    const float* __restrict__ W1c, const float* __restrict__ b1c,
    const float* __restrict__ W1r, const float* __restrict__ b1r,
    const float* __restrict__ W1l, const float* __restrict__ b1l,
    float* __restrict__ out)
{
    __shared__ float As[2][BK*AST];
    __shared__ float Bs[2][BK*BN];
    const int g = blockIdx.x;
    const int tid = threadIdx.x;

    if (g < GEMM_BLOCKS) {
        const int nt = g % 48;
        const int r  = g / 48;
        const int mt = r >> 1;
        const int ks = r & 1;
        const int t  = nt >> 4;
        const int s  = (nt >> 3) & 1;
        const int f0 = (nt & 7) * BN;
        const float* W1 = (t==0 ? W1c : (t==1 ? W1r : W1l)) + (size_t)s * C3 * FF;
        const float* b1 = (t==0 ? b1c : (t==1 ? b1r : b1l));
        const int m0 = mt * BM;
        const int kbase = ks * 384;

        const int arow = tid >> 2, av = tid & 3;          // A load
        const int kr = tid >> 4, fo = (tid & 15) * 4;     // B load
        const int rg = tid >> 4, cg = tid & 15;           // compute: 4m x 4n

        unsigned long long acc2[4][2];
        #pragma unroll
        for (int a = 0; a < 4; a++) { acc2[a][0] = 0ull; acc2[a][1] = 0ull; }

        float4 pa, pb;
        {
            const int c0 = kbase;
            const float* segp = (c0 < 256) ? geo : ((c0 < 512) ? app : con);
            pa = *(const float4*)(segp + (size_t)(m0 + arow) * HH + (c0 & 255) + av * 4);
            pb = *(const float4*)(W1 + (size_t)(c0 + kr) * FF + f0 + fo);
        }
        {
            As[0][(av*4+0)*AST + arow] = pa.x;
            As[0][(av*4+1)*AST + arow] = pa.y;
            As[0][(av*4+2)*AST + arow] = pa.z;
            As[0][(av*4+3)*AST + arow] = pa.w;
            *(float4*)&Bs[0][kr*BN + fo] = pb;
        }
        __syncthreads();

        for (int kt = 0; kt < NKS; kt++) {
            const int cur = kt & 1;
            const int nxt = cur ^ 1;
            if (kt + 1 < NKS) {
                const int c0 = kbase + (kt + 1) * BK;
                const float* segp = (c0 < 256) ? geo : ((c0 < 512) ? app : con);
                pa = *(const float4*)(segp + (size_t)(m0 + arow) * HH + (c0 & 255) + av * 4);
                pb = *(const float4*)(W1 + (size_t)(c0 + kr) * FF + f0 + fo);
            }
            #pragma unroll
            for (int k = 0; k < BK; k++) {
                const float4 a4 = *(const float4*)&As[cur][k*AST + rg*4];
                const ulonglong2 b2v = *(const ulonglong2*)&Bs[cur][k*BN + cg*4];
                float avv[4] = {a4.x, a4.y, a4.z, a4.w};
                #pragma unroll
                for (int a = 0; a < 4; a++) {
                    unsigned long long ad;
                    PACKDUP(ad, avv[a]);
                    FFMA2(acc2[a][0], ad, b2v.x);
                    FFMA2(acc2[a][1], ad, b2v.y);
                }
            }
            if (kt + 1 < NKS) {
                __syncthreads();
                As[nxt][(av*4+0)*AST + arow] = pa.x;
                As[nxt][(av*4+1)*AST + arow] = pa.y;
                As[nxt][(av*4+2)*AST + arow] = pa.z;
                As[nxt][(av*4+3)*AST + arow] = pa.w;
                *(float4*)&Bs[nxt][kr*BN + fo] = pb;
                __syncthreads();
            }
        }

        // epilogue
        const bool addb = (s == 1) && (ks == 0);
        float bv[4] = {0.f, 0.f, 0.f, 0.f};
        if (addb) {
            const float4 tb = *(const float4*)(b1 + f0 + cg*4);
            bv[0]=tb.x; bv[1]=tb.y; bv[2]=tb.z; bv[3]=tb.w;
        }
        const size_t hb = ((size_t)((t*2 + s) * 2 + ks)) * MM * FF;
        #pragma unroll
        for (int a = 0; a < 4; a++) {
            const int m = m0 + rg*4 + a;
            unsigned int lo0, hi0, lo1, hi1;
            UNPK(lo0, hi0, acc2[a][0]);
            UNPK(lo1, hi1, acc2[a][1]);
            float v0 = __uint_as_float(lo0) + bv[0];
            float v1 = __uint_as_float(hi0) + bv[1];
            float v2 = __uint_as_float(lo1) + bv[2];
            float v3 = __uint_as_float(hi1) + bv[3];
            *(float4*)(g_PQ + hb + (size_t)m * FF + f0 + cg*4) = make_float4(v0, v1, v2, v3);
        }
    } else {
        const int wb = g - GEMM_BLOCKS;    // 0..1599
        const int b = wb / 800;
        const int rem = wb % 800;
        const int i = rem / 5;
        const int j0 = (rem % 5) * 16;     // first half: j in [0,80)
        writer_role(b, i, j0, geo, app, con, out, tid);
    }
}

// ---------------- Kernel 2: logits (32i x 32j, acc[4]) + writer half B ----------------
#define LG_BLOCKS 150
#define WRB_BLOCKS 1600

__global__ __launch_bounds__(256) void k2_lg_wr(
    const float* __restrict__ geo, const float* __restrict__ app, const float* __restrict__ con,
    float* __restrict__ out,
    const float* __restrict__ W2c, const float* __restrict__ b2c,
    const float* __restrict__ W2r, const float* __restrict__ b2r,
    const float* __restrict__ W2l, const float* __restrict__ b2l)
{
    __shared__ float sP[32 * 132];
    __shared__ float sQ[32 * 128];
    __shared__ float sW[128];
    const int g = blockIdx.x;
    const int tid = threadIdx.x;

    if (g < LG_BLOCKS) {
        const int t = g / 50;
        const int r50 = g % 50;
        const int b = r50 / 25;
        const int r25 = r50 % 25;
        const int i0 = (r25 / 5) * 32;
        const int j0 = (r25 % 5) * 32;
        const float* W2 = (t==0 ? W2c : (t==1 ? W2r : W2l));
        const float* b2 = (t==0 ? b2c : (t==1 ? b2r : b2l));
        const size_t boff = (size_t)b * NN * FF;
        const float* P0 = g_PQ + ((size_t)((t*2+0)*2+0)) * MM * FF + boff;
        const float* P1 = g_PQ + ((size_t)((t*2+0)*2+1)) * MM * FF + boff;
        const float* Q0 = g_PQ + ((size_t)((t*2+1)*2+0)) * MM * FF + boff;
        const float* Q1 = g_PQ + ((size_t)((t*2+1)*2+1)) * MM * FF + boff;
        const int il = tid >> 5, jl = tid & 31;
        const int lr = tid >> 3, lv = tid & 7;

        float acc[4] = {0.f, 0.f, 0.f, 0.f};
        for (int fc = 0; fc < 4; fc++) {
            const int f0 = fc * 128;
            {
                const size_t ro = (size_t)(j0 + lr) * FF + f0;
                float* dp = sP + lr * 132;
                #pragma unroll
                for (int u = 0; u < 4; u++) {
                    const int fl = (lv + u * 8) * 4;
                    const float4 x = *(const float4*)(P0 + ro + fl);
                    const float4 y = *(const float4*)(P1 + ro + fl);
                    *(float4*)(dp + fl) = make_float4(x.x+y.x, x.y+y.y, x.z+y.z, x.w+y.w);
                }
            }
            {
                const size_t ro = (size_t)(i0 + lr) * FF + f0;
                float* dp = sQ + lr * 128;
                #pragma unroll
                for (int u = 0; u < 4; u++) {
                    const int fl = (lv + u * 8) * 4;
                    const float4 x = *(const float4*)(Q0 + ro + fl);
                    const float4 y = *(const float4*)(Q1 + ro + fl);
                    *(float4*)(dp + fl) = make_float4(x.x+y.x, x.y+y.y, x.z+y.z, x.w+y.w);
                }
            }
            if (tid < 128) {
                const float2 w2v = ((const float2*)W2)[f0 + tid];
                sW[tid] = w2v.x - w2v.y;
            }
            __syncthreads();

            const float* pr = sP + jl * 132;
            const float* q0 = sQ + (il * 4) * 128;
            #pragma unroll 4
            for (int f = 0; f < 128; f += 4) {
                const float4 p = *(const float4*)(pr + f);
                const float4 w = *(const float4*)(sW + f);
                #pragma unroll
                for (int a = 0; a < 4; a++) {
                    const float4 q = *(const float4*)(q0 + a * 128 + f);
                    acc[a] = fmaf(fmaxf(p.x + q.x, 0.f), w.x, acc[a]);
                    acc[a] = fmaf(fmaxf(p.y + q.y, 0.f), w.y, acc[a]);
                    acc[a] = fmaf(fmaxf(p.z + q.z, 0.f), w.z, acc[a]);
                    acc[a] = fmaf(fmaxf(p.w + q.w, 0.f), w.w, acc[a]);
                }
            }
            __syncthreads();
        }

        const float bd = b2[0] - b2[1];
        float2* o = (float2*)(out + (size_t)t * LOGIT_ELEMS) + (size_t)b * NP;
        const int j = j0 + jl;
        #pragma unroll
        for (int a = 0; a < 4; a++) {
            const float d = acc[a] + bd;
            const float p0 = 1.0f / (1.0f + __expf(-d));
            o[(size_t)(i0 + il*4 + a) * NN + j] = make_float2(p0, 1.0f - p0);
        }
    } else {
        const int wb = g - LG_BLOCKS;      // 0..1599
        const int b = wb / 800;
        const int rem = wb % 800;
        const int i = rem / 5;
        const int j0 = (rem % 5 + 5) * 16; // second half: j in [80,160)
        writer_role(b, i, j0, geo, app, con, out, tid);
    }
}

extern "C" void kernel_launch(void* const* d_in, const int* in_sizes, int n_in,
                              void* d_out, int out_size) {
    const float* geo = (const float*)d_in[0];
    const float* app = (const float*)d_in[1];
    const float* con = (const float*)d_in[2];
    const float* W1c = (const float*)d_in[3];
    const float* b1c = (const float*)d_in[4];
    const float* W2c = (const float*)d_in[5];
    const float* b2c = (const float*)d_in[6];
    const float* W1r = (const float*)d_in[7];
    const float* b1r = (const float*)d_in[8];
    const float* W2r = (const float*)d_in[9];
    const float* b2r = (const float*)d_in[10];
    const float* W1l = (const float*)d_in[11];
    const float* b1l = (const float*)d_in[12];
    const float* W2l = (const float*)d_in[13];
    const float* b2l = (const float*)d_in[14];
    float* out = (float*)d_out;

    k1_gemm_wr<<<GEMM_BLOCKS + WRA_BLOCKS, 256>>>(geo, app, con,
                                                  W1c, b1c, W1r, b1r, W1l, b1l, out);
    k2_lg_wr<<<LG_BLOCKS + WRB_BLOCKS, 256>>>(geo, app, con, out,
                                              W2c, b2c, W2r, b2r, W2l, b2l);
}